// round 3
// baseline (speedup 1.0000x reference)
#include <cuda_runtime.h>
#include <cuda_bf16.h>
#include <cstdint>

#define NV 100000
#define NE 20000
#define NE_PAD 20032            // 313 * 64
#define D  256
#define NNZ_MAX 800000

// ----- device scratch (no allocations allowed) -----
__device__ int   g_eptr[NE + 1];
__device__ int   g_vptr[NV + 1];
__device__ int   g_ecur[NE];          // counts, then fill cursors
__device__ int   g_vcur[NV];
__device__ int   g_ecol[NNZ_MAX];     // vertex ids grouped by edge
__device__ int   g_vcol[NNZ_MAX];     // edge ids grouped by vertex
__device__ float g_A[(size_t)NE_PAD * D]; // per-edge mean of incident X rows
__device__ float g_Y[(size_t)NE_PAD * D]; // edge features after GEMM

// ---------------------------------------------------------------------------
// CSR build step 1: degree histograms, 4 entries per thread for MLP.
// ---------------------------------------------------------------------------
__global__ void hist(const int4* __restrict__ vidx4, const int4* __restrict__ eidx4,
                     int nnz4) {
    int i = blockIdx.x * blockDim.x + threadIdx.x;
    if (i >= nnz4) return;
    int4 e = __ldg(eidx4 + i);
    int4 v = __ldg(vidx4 + i);
    atomicAdd(g_ecur + e.x, 1); atomicAdd(g_ecur + e.y, 1);
    atomicAdd(g_ecur + e.z, 1); atomicAdd(g_ecur + e.w, 1);
    atomicAdd(g_vcur + v.x, 1); atomicAdd(g_vcur + v.y, 1);
    atomicAdd(g_vcur + v.z, 1); atomicAdd(g_vcur + v.w, 1);
}

// ---------------------------------------------------------------------------
// CSR build step 2: both exclusive scans in one kernel (block 0: edges,
// block 1: vertices). Reads counts from cur, writes ptr, resets cur to starts.
// ---------------------------------------------------------------------------
__global__ void scan_both() {
    __shared__ int partial[1024];
    int* cur; int* ptr; int n;
    if (blockIdx.x == 0) { cur = g_ecur; ptr = g_eptr; n = NE; }
    else                 { cur = g_vcur; ptr = g_vptr; n = NV; }
    const int tid = threadIdx.x;
    const int chunk = (n + 1023) / 1024;
    const int start = min(tid * chunk, n);
    const int end = min(start + chunk, n);
    int s = 0;
    for (int i = start; i < end; i++) s += cur[i];
    partial[tid] = s;
    __syncthreads();
    for (int off = 1; off < 1024; off <<= 1) {
        int v = (tid >= off) ? partial[tid - off] : 0;
        __syncthreads();
        partial[tid] += v;
        __syncthreads();
    }
    int run = (tid == 0) ? 0 : partial[tid - 1];
    for (int i = start; i < end; i++) {
        int c = cur[i];
        ptr[i] = run;
        cur[i] = run;
        run += c;
    }
    if (tid == 1023) ptr[n] = run;
}

// ---------------------------------------------------------------------------
// CSR build step 3: fill adjacency lists, 4 entries per thread.
// ---------------------------------------------------------------------------
__global__ void fill(const int4* __restrict__ vidx4, const int4* __restrict__ eidx4,
                     int nnz4) {
    int i = blockIdx.x * blockDim.x + threadIdx.x;
    if (i >= nnz4) return;
    int4 e = __ldg(eidx4 + i);
    int4 v = __ldg(vidx4 + i);
    int p0 = atomicAdd(g_ecur + e.x, 1);
    int p1 = atomicAdd(g_ecur + e.y, 1);
    int p2 = atomicAdd(g_ecur + e.z, 1);
    int p3 = atomicAdd(g_ecur + e.w, 1);
    g_ecol[p0] = v.x; g_ecol[p1] = v.y; g_ecol[p2] = v.z; g_ecol[p3] = v.w;
    int q0 = atomicAdd(g_vcur + v.x, 1);
    int q1 = atomicAdd(g_vcur + v.y, 1);
    int q2 = atomicAdd(g_vcur + v.z, 1);
    int q3 = atomicAdd(g_vcur + v.w, 1);
    g_vcol[q0] = e.x; g_vcol[q1] = e.y; g_vcol[q2] = e.z; g_vcol[q3] = e.w;
}

// ---------------------------------------------------------------------------
// Phase v2e: A[e] = mean of X[v] over incident vertices. 64 thr/edge,
// 4-way unrolled gather loop for MLP.
// ---------------------------------------------------------------------------
__global__ void gather_v2e(const float4* __restrict__ X4) {
    const int e = blockIdx.x * 4 + (threadIdx.x >> 6);
    const int lane = threadIdx.x & 63;
    if (e >= NE) return;
    const int beg = g_eptr[e], end = g_eptr[e + 1];
    float4 acc = make_float4(0.f, 0.f, 0.f, 0.f);
    int j = beg;
    for (; j + 3 < end; j += 4) {
        int v0 = __ldg(g_ecol + j);
        int v1 = __ldg(g_ecol + j + 1);
        int v2 = __ldg(g_ecol + j + 2);
        int v3 = __ldg(g_ecol + j + 3);
        float4 a = __ldg(X4 + (size_t)v0 * 64 + lane);
        float4 b = __ldg(X4 + (size_t)v1 * 64 + lane);
        float4 c = __ldg(X4 + (size_t)v2 * 64 + lane);
        float4 d = __ldg(X4 + (size_t)v3 * 64 + lane);
        acc.x += (a.x + b.x) + (c.x + d.x);
        acc.y += (a.y + b.y) + (c.y + d.y);
        acc.z += (a.z + b.z) + (c.z + d.z);
        acc.w += (a.w + b.w) + (c.w + d.w);
    }
    for (; j < end; j++) {
        int v0 = __ldg(g_ecol + j);
        float4 a = __ldg(X4 + (size_t)v0 * 64 + lane);
        acc.x += a.x; acc.y += a.y; acc.z += a.z; acc.w += a.w;
    }
    float s = 1.0f / fmaxf((float)(end - beg), 1.0f);
    acc.x *= s; acc.y *= s; acc.z *= s; acc.w *= s;
    *(float4*)(g_A + (size_t)e * D + lane * 4) = acc;
}

// ---------------------------------------------------------------------------
// GEMM: Y = A @ W + b with packed f32x2 FMA.
// BM=64, BN=128, BK=16, 256 threads, 4x8 micro-tile (16 FFMA2/k/thread).
// M padded to NE_PAD so no bounds checks.
// ---------------------------------------------------------------------------
__device__ __forceinline__ void fma2(unsigned long long& d,
                                     unsigned long long a,
                                     unsigned long long b) {
    asm("fma.rn.f32x2 %0, %1, %2, %0;" : "+l"(d) : "l"(a), "l"(b));
}
__device__ __forceinline__ unsigned long long dup2(float v) {
    unsigned long long r;
    asm("mov.b64 %0, {%1, %1};" : "=l"(r) : "f"(v));
    return r;
}

__global__ void gemm_bias(const float* __restrict__ W,
                          const float* __restrict__ bias) {
    __shared__ float As[16][64];
    __shared__ float Ws[16][128];
    const int tid = threadIdx.x;
    const int row0 = blockIdx.x * 64;
    const int col0 = blockIdx.y * 128;
    const int ty = tid >> 4;            // 0..15 -> rows ty*4..ty*4+3
    const int tx = tid & 15;            // 0..15 -> cols tx*8..tx*8+7

    unsigned long long acc[4][4];
#pragma unroll
    for (int i = 0; i < 4; i++)
#pragma unroll
        for (int j = 0; j < 4; j++) acc[i][j] = 0ull;

    const int ar = tid >> 2;            // 0..63
    const int kq = (tid & 3) * 4;       // 0,4,8,12
    const float* Arow = g_A + (size_t)(row0 + ar) * D;
    const int wr = tid >> 4;            // 0..15
    const int wc = (tid & 15) * 8;      // 0..120

    for (int k0 = 0; k0 < D; k0 += 16) {
        float4 a = *(const float4*)(Arow + k0 + kq);
        As[kq + 0][ar] = a.x;
        As[kq + 1][ar] = a.y;
        As[kq + 2][ar] = a.z;
        As[kq + 3][ar] = a.w;
        const float* wsrc = W + (size_t)(k0 + wr) * D + col0 + wc;
        *(float4*)&Ws[wr][wc]     = *(const float4*)(wsrc);
        *(float4*)&Ws[wr][wc + 4] = *(const float4*)(wsrc + 4);
        __syncthreads();
#pragma unroll
        for (int k = 0; k < 16; k++) {
            float4 aq = *(const float4*)&As[k][ty * 4];
            ulonglong2 w01 = *(const ulonglong2*)&Ws[k][tx * 8];
            ulonglong2 w23 = *(const ulonglong2*)&Ws[k][tx * 8 + 4];
            unsigned long long ad0 = dup2(aq.x);
            unsigned long long ad1 = dup2(aq.y);
            unsigned long long ad2 = dup2(aq.z);
            unsigned long long ad3 = dup2(aq.w);
            fma2(acc[0][0], ad0, w01.x); fma2(acc[0][1], ad0, w01.y);
            fma2(acc[0][2], ad0, w23.x); fma2(acc[0][3], ad0, w23.y);
            fma2(acc[1][0], ad1, w01.x); fma2(acc[1][1], ad1, w01.y);
            fma2(acc[1][2], ad1, w23.x); fma2(acc[1][3], ad1, w23.y);
            fma2(acc[2][0], ad2, w01.x); fma2(acc[2][1], ad2, w01.y);
            fma2(acc[2][2], ad2, w23.x); fma2(acc[2][3], ad2, w23.y);
            fma2(acc[3][0], ad3, w01.x); fma2(acc[3][1], ad3, w01.y);
            fma2(acc[3][2], ad3, w23.x); fma2(acc[3][3], ad3, w23.y);
        }
        __syncthreads();
    }

    float4 b0 = *(const float4*)(bias + col0 + tx * 8);
    float4 b1 = *(const float4*)(bias + col0 + tx * 8 + 4);
    float bb[8] = {b0.x, b0.y, b0.z, b0.w, b1.x, b1.y, b1.z, b1.w};
#pragma unroll
    for (int i = 0; i < 4; i++) {
        float o[8];
#pragma unroll
        for (int j = 0; j < 4; j++) {
            float lo, hi;
            asm("mov.b64 {%0, %1}, %2;" : "=f"(lo), "=f"(hi) : "l"(acc[i][j]));
            o[2 * j]     = lo + bb[2 * j];
            o[2 * j + 1] = hi + bb[2 * j + 1];
        }
        float* dst = g_Y + (size_t)(row0 + ty * 4 + i) * D + col0 + tx * 8;
        *(float4*)(dst)     = make_float4(o[0], o[1], o[2], o[3]);
        *(float4*)(dst + 4) = make_float4(o[4], o[5], o[6], o[7]);
    }
}

// ---------------------------------------------------------------------------
// Phase e2v: out[v] = relu(mean of Y[e] over incident edges). 64 thr/vertex,
// 4-way unrolled, streaming store of d_out (keep Y resident in L2).
// ---------------------------------------------------------------------------
__global__ void gather_e2v(float4* __restrict__ out) {
    const int v = blockIdx.x * 4 + (threadIdx.x >> 6);
    const int lane = threadIdx.x & 63;
    if (v >= NV) return;
    const int beg = g_vptr[v], end = g_vptr[v + 1];
    const float4* Y4 = (const float4*)g_Y;
    float4 acc = make_float4(0.f, 0.f, 0.f, 0.f);
    int j = beg;
    for (; j + 3 < end; j += 4) {
        int e0 = __ldg(g_vcol + j);
        int e1 = __ldg(g_vcol + j + 1);
        int e2 = __ldg(g_vcol + j + 2);
        int e3 = __ldg(g_vcol + j + 3);
        float4 a = __ldg(Y4 + (size_t)e0 * 64 + lane);
        float4 b = __ldg(Y4 + (size_t)e1 * 64 + lane);
        float4 c = __ldg(Y4 + (size_t)e2 * 64 + lane);
        float4 d = __ldg(Y4 + (size_t)e3 * 64 + lane);
        acc.x += (a.x + b.x) + (c.x + d.x);
        acc.y += (a.y + b.y) + (c.y + d.y);
        acc.z += (a.z + b.z) + (c.z + d.z);
        acc.w += (a.w + b.w) + (c.w + d.w);
    }
    for (; j < end; j++) {
        int e0 = __ldg(g_vcol + j);
        float4 a = __ldg(Y4 + (size_t)e0 * 64 + lane);
        acc.x += a.x; acc.y += a.y; acc.z += a.z; acc.w += a.w;
    }
    float s = 1.0f / fmaxf((float)(end - beg), 1.0f);
    float4 o;
    o.x = fmaxf(acc.x * s, 0.0f);
    o.y = fmaxf(acc.y * s, 0.0f);
    o.z = fmaxf(acc.z * s, 0.0f);
    o.w = fmaxf(acc.w * s, 0.0f);
    __stcs(out + (size_t)v * 64 + lane, o);
}

extern "C" void kernel_launch(void* const* d_in, const int* in_sizes, int n_in,
                              void* d_out, int out_size) {
    const float* X    = (const float*)d_in[0];
    const float* W    = (const float*)d_in[1];
    const float* bias = (const float*)d_in[2];
    const int* vidx   = (const int*)d_in[3];
    const int* eidx   = (const int*)d_in[4];
    const int nnz     = in_sizes[3];

    void *pEcur, *pVcur;
    cudaGetSymbolAddress(&pEcur, g_ecur);
    cudaGetSymbolAddress(&pVcur, g_vcur);
    cudaMemsetAsync(pEcur, 0, sizeof(int) * NE);
    cudaMemsetAsync(pVcur, 0, sizeof(int) * NV);

    int nnz4 = nnz / 4;   // NNZ = 800000, divisible by 4
    int nb4 = (nnz4 + 255) / 256;
    hist<<<nb4, 256>>>((const int4*)vidx, (const int4*)eidx, nnz4);
    scan_both<<<2, 1024>>>();
    fill<<<nb4, 256>>>((const int4*)vidx, (const int4*)eidx, nnz4);

    gather_v2e<<<(NE + 3) / 4, 256>>>((const float4*)X);

    dim3 ggrid(NE_PAD / 64, D / 128);
    gemm_bias<<<ggrid, 256>>>(W, bias);

    gather_e2v<<<(NV + 3) / 4, 256>>>((float4*)d_out);
}

// round 4
// speedup vs baseline: 1.2167x; 1.2167x over previous
#include <cuda_runtime.h>
#include <cuda_fp16.h>
#include <cstdint>

#define NV 100000
#define NE 20000
#define NE_PAD 20096            // 157 * 128
#define D  256
#define NNZ_MAX 800000

// ----- device scratch (no allocations allowed) -----
__device__ int    g_eptr[NE + 1];
__device__ int    g_vptr[NV + 1];
__device__ int    g_cur[NE + NV];          // edge counts then vertex counts
__device__ int    g_ecol[NNZ_MAX];         // vertex ids grouped by edge
__device__ int    g_vcol[NNZ_MAX];         // edge ids grouped by vertex
__device__ __half g_Xh[(size_t)NV * D];    // fp16 copy of X (51.2 MB)
__device__ float  g_A[(size_t)NE_PAD * D]; // per-edge mean of X rows (fp32)
__device__ __half g_Y[(size_t)NE_PAD * D]; // edge features after GEMM (fp16)

// ---------------------------------------------------------------------------
// prep: heterogeneous kernel.
//  blocks [0, histBlocks): degree histograms (4 entries/thread)
//  blocks [histBlocks, ...): convert X fp32 -> fp16 (8 elements/thread)
// The DRAM-streaming conversion overlaps the latency-bound atomics.
// ---------------------------------------------------------------------------
__global__ void prep(const int4* __restrict__ vidx4,
                     const int4* __restrict__ eidx4, int nnz4,
                     const float4* __restrict__ X4, int histBlocks) {
    if ((int)blockIdx.x < histBlocks) {
        int i = blockIdx.x * blockDim.x + threadIdx.x;
        if (i >= nnz4) return;
        int4 e = __ldg(eidx4 + i);
        int4 v = __ldg(vidx4 + i);
        atomicAdd(g_cur + e.x, 1); atomicAdd(g_cur + e.y, 1);
        atomicAdd(g_cur + e.z, 1); atomicAdd(g_cur + e.w, 1);
        atomicAdd(g_cur + NE + v.x, 1); atomicAdd(g_cur + NE + v.y, 1);
        atomicAdd(g_cur + NE + v.z, 1); atomicAdd(g_cur + NE + v.w, 1);
    } else {
        int i = (blockIdx.x - histBlocks) * blockDim.x + threadIdx.x; // 0..3.2M-1
        float4 a = __ldg(X4 + (size_t)i * 2);
        float4 b = __ldg(X4 + (size_t)i * 2 + 1);
        __half2 h0 = __floats2half2_rn(a.x, a.y);
        __half2 h1 = __floats2half2_rn(a.z, a.w);
        __half2 h2 = __floats2half2_rn(b.x, b.y);
        __half2 h3 = __floats2half2_rn(b.z, b.w);
        uint4 o;
        o.x = *(unsigned*)&h0; o.y = *(unsigned*)&h1;
        o.z = *(unsigned*)&h2; o.w = *(unsigned*)&h3;
        ((uint4*)g_Xh)[i] = o;
    }
}

// ---------------------------------------------------------------------------
// scan_both: block 0 scans edge counts, block 1 vertex counts.
// Writes row_ptr; resets cursors to row starts.
// ---------------------------------------------------------------------------
__global__ void scan_both() {
    __shared__ int partial[1024];
    int* cur; int* ptr; int n;
    if (blockIdx.x == 0) { cur = g_cur;      ptr = g_eptr; n = NE; }
    else                 { cur = g_cur + NE; ptr = g_vptr; n = NV; }
    const int tid = threadIdx.x;
    const int chunk = (n + 1023) / 1024;
    const int start = min(tid * chunk, n);
    const int end = min(start + chunk, n);
    int s = 0;
    for (int i = start; i < end; i++) s += cur[i];
    partial[tid] = s;
    __syncthreads();
    for (int off = 1; off < 1024; off <<= 1) {
        int v = (tid >= off) ? partial[tid - off] : 0;
        __syncthreads();
        partial[tid] += v;
        __syncthreads();
    }
    int run = (tid == 0) ? 0 : partial[tid - 1];
    for (int i = start; i < end; i++) {
        int c = cur[i];
        ptr[i] = run;
        cur[i] = run;
        run += c;
    }
    if (tid == 1023) ptr[n] = run;
}

// ---------------------------------------------------------------------------
// fill: adjacency lists, 4 entries/thread.
// ---------------------------------------------------------------------------
__global__ void fill(const int4* __restrict__ vidx4,
                     const int4* __restrict__ eidx4, int nnz4) {
    int i = blockIdx.x * blockDim.x + threadIdx.x;
    if (i >= nnz4) return;
    int4 e = __ldg(eidx4 + i);
    int4 v = __ldg(vidx4 + i);
    int p0 = atomicAdd(g_cur + e.x, 1);
    int p1 = atomicAdd(g_cur + e.y, 1);
    int p2 = atomicAdd(g_cur + e.z, 1);
    int p3 = atomicAdd(g_cur + e.w, 1);
    g_ecol[p0] = v.x; g_ecol[p1] = v.y; g_ecol[p2] = v.z; g_ecol[p3] = v.w;
    int q0 = atomicAdd(g_cur + NE + v.x, 1);
    int q1 = atomicAdd(g_cur + NE + v.y, 1);
    int q2 = atomicAdd(g_cur + NE + v.z, 1);
    int q3 = atomicAdd(g_cur + NE + v.w, 1);
    g_vcol[q0] = e.x; g_vcol[q1] = e.y; g_vcol[q2] = e.z; g_vcol[q3] = e.w;
}

// fp16x8 accumulate into 8 fp32
__device__ __forceinline__ void accum8(float* a, uint4 h) {
    __half2* p = (__half2*)&h;
    float2 f0 = __half22float2(p[0]);
    float2 f1 = __half22float2(p[1]);
    float2 f2 = __half22float2(p[2]);
    float2 f3 = __half22float2(p[3]);
    a[0] += f0.x; a[1] += f0.y; a[2] += f1.x; a[3] += f1.y;
    a[4] += f2.x; a[5] += f2.y; a[6] += f3.x; a[7] += f3.y;
}

// ---------------------------------------------------------------------------
// Phase v2e: A[e] = mean of Xh[v]. One warp per edge, lane = 8 halves (16 B).
// ---------------------------------------------------------------------------
__global__ void gather_v2e() {
    const int e = blockIdx.x * 8 + (threadIdx.x >> 5);
    const int lane = threadIdx.x & 31;
    if (e >= NE) return;
    const int beg = g_eptr[e], end = g_eptr[e + 1];
    const uint4* Xh4 = (const uint4*)g_Xh;   // 32 uint4 per row
    float acc[8] = {};
    int j = beg;
    for (; j + 3 < end; j += 4) {
        int v0 = __ldg(g_ecol + j);
        int v1 = __ldg(g_ecol + j + 1);
        int v2 = __ldg(g_ecol + j + 2);
        int v3 = __ldg(g_ecol + j + 3);
        uint4 h0 = __ldg(Xh4 + (size_t)v0 * 32 + lane);
        uint4 h1 = __ldg(Xh4 + (size_t)v1 * 32 + lane);
        uint4 h2 = __ldg(Xh4 + (size_t)v2 * 32 + lane);
        uint4 h3 = __ldg(Xh4 + (size_t)v3 * 32 + lane);
        accum8(acc, h0); accum8(acc, h1); accum8(acc, h2); accum8(acc, h3);
    }
    for (; j < end; j++) {
        int v0 = __ldg(g_ecol + j);
        uint4 h0 = __ldg(Xh4 + (size_t)v0 * 32 + lane);
        accum8(acc, h0);
    }
    float s = 1.0f / fmaxf((float)(end - beg), 1.0f);
    float* dst = g_A + (size_t)e * D + lane * 8;
    *(float4*)dst = make_float4(acc[0] * s, acc[1] * s, acc[2] * s, acc[3] * s);
    *(float4*)(dst + 4) = make_float4(acc[4] * s, acc[5] * s, acc[6] * s, acc[7] * s);
}

// ---------------------------------------------------------------------------
// GEMM: Y = A @ W + b (fp16 out). BM=BN=128, BK=16, 256 threads,
// 8x8 micro-tile via packed fma.rn.f32x2 (32 FFMA2 per k per thread).
// ---------------------------------------------------------------------------
__device__ __forceinline__ void fma2(unsigned long long& d,
                                     unsigned long long a,
                                     unsigned long long b) {
    asm("fma.rn.f32x2 %0, %1, %2, %0;" : "+l"(d) : "l"(a), "l"(b));
}
__device__ __forceinline__ unsigned long long dup2(float v) {
    unsigned long long r;
    asm("mov.b64 %0, {%1, %1};" : "=l"(r) : "f"(v));
    return r;
}

__global__ __launch_bounds__(256, 2) void gemm_bias(const float* __restrict__ W,
                                                    const float* __restrict__ bias) {
    __shared__ float As[16][128];
    __shared__ float Ws[16][128];
    const int tid = threadIdx.x;
    const int row0 = blockIdx.x * 128;
    const int col0 = blockIdx.y * 128;
    const int ty = tid >> 4;            // 0..15 -> rows ty*8..
    const int tx = tid & 15;            // 0..15 -> cols tx*8..

    unsigned long long acc[8][4];
#pragma unroll
    for (int i = 0; i < 8; i++)
#pragma unroll
        for (int j = 0; j < 4; j++) acc[i][j] = 0ull;

    const int ar = tid >> 1;            // 0..127
    const int kq = (tid & 1) * 8;       // 0 or 8
    const float* Arow = g_A + (size_t)(row0 + ar) * D;
    const int wr = tid >> 4;            // 0..15
    const int wc = (tid & 15) * 8;      // 0..120

    for (int k0 = 0; k0 < D; k0 += 16) {
        float4 a0 = *(const float4*)(Arow + k0 + kq);
        float4 a1 = *(const float4*)(Arow + k0 + kq + 4);
        As[kq + 0][ar] = a0.x; As[kq + 1][ar] = a0.y;
        As[kq + 2][ar] = a0.z; As[kq + 3][ar] = a0.w;
        As[kq + 4][ar] = a1.x; As[kq + 5][ar] = a1.y;
        As[kq + 6][ar] = a1.z; As[kq + 7][ar] = a1.w;
        const float* wsrc = W + (size_t)(k0 + wr) * D + col0 + wc;
        *(float4*)&Ws[wr][wc]     = *(const float4*)(wsrc);
        *(float4*)&Ws[wr][wc + 4] = *(const float4*)(wsrc + 4);
        __syncthreads();
#pragma unroll
        for (int k = 0; k < 16; k++) {
            float4 aq0 = *(const float4*)&As[k][ty * 8];
            float4 aq1 = *(const float4*)&As[k][ty * 8 + 4];
            ulonglong2 w01 = *(const ulonglong2*)&Ws[k][tx * 8];
            ulonglong2 w23 = *(const ulonglong2*)&Ws[k][tx * 8 + 4];
            unsigned long long ad[8];
            ad[0] = dup2(aq0.x); ad[1] = dup2(aq0.y);
            ad[2] = dup2(aq0.z); ad[3] = dup2(aq0.w);
            ad[4] = dup2(aq1.x); ad[5] = dup2(aq1.y);
            ad[6] = dup2(aq1.z); ad[7] = dup2(aq1.w);
#pragma unroll
            for (int i = 0; i < 8; i++) {
                fma2(acc[i][0], ad[i], w01.x);
                fma2(acc[i][1], ad[i], w01.y);
                fma2(acc[i][2], ad[i], w23.x);
                fma2(acc[i][3], ad[i], w23.y);
            }
        }
        __syncthreads();
    }

    float4 b0 = *(const float4*)(bias + col0 + tx * 8);
    float4 b1 = *(const float4*)(bias + col0 + tx * 8 + 4);
    float bb[8] = {b0.x, b0.y, b0.z, b0.w, b1.x, b1.y, b1.z, b1.w};
#pragma unroll
    for (int i = 0; i < 8; i++) {
        float o[8];
#pragma unroll
        for (int j = 0; j < 4; j++) {
            float lo, hi;
            asm("mov.b64 {%0, %1}, %2;" : "=f"(lo), "=f"(hi) : "l"(acc[i][j]));
            o[2 * j]     = lo + bb[2 * j];
            o[2 * j + 1] = hi + bb[2 * j + 1];
        }
        __half2 h0 = __floats2half2_rn(o[0], o[1]);
        __half2 h1 = __floats2half2_rn(o[2], o[3]);
        __half2 h2 = __floats2half2_rn(o[4], o[5]);
        __half2 h3 = __floats2half2_rn(o[6], o[7]);
        uint4 pk;
        pk.x = *(unsigned*)&h0; pk.y = *(unsigned*)&h1;
        pk.z = *(unsigned*)&h2; pk.w = *(unsigned*)&h3;
        size_t off = (size_t)(row0 + ty * 8 + i) * D + col0 + tx * 8;
        *(uint4*)(g_Y + off) = pk;
    }
}

// ---------------------------------------------------------------------------
// Phase e2v: out[v] = relu(mean of Y[e]). One warp per vertex; streaming store.
// ---------------------------------------------------------------------------
__global__ void gather_e2v(float4* __restrict__ out) {
    const int v = blockIdx.x * 8 + (threadIdx.x >> 5);
    const int lane = threadIdx.x & 31;
    if (v >= NV) return;
    const int beg = g_vptr[v], end = g_vptr[v + 1];
    const uint4* Y4 = (const uint4*)g_Y;   // 32 uint4 per row
    float acc[8] = {};
    int j = beg;
    for (; j + 3 < end; j += 4) {
        int e0 = __ldg(g_vcol + j);
        int e1 = __ldg(g_vcol + j + 1);
        int e2 = __ldg(g_vcol + j + 2);
        int e3 = __ldg(g_vcol + j + 3);
        uint4 h0 = __ldg(Y4 + (size_t)e0 * 32 + lane);
        uint4 h1 = __ldg(Y4 + (size_t)e1 * 32 + lane);
        uint4 h2 = __ldg(Y4 + (size_t)e2 * 32 + lane);
        uint4 h3 = __ldg(Y4 + (size_t)e3 * 32 + lane);
        accum8(acc, h0); accum8(acc, h1); accum8(acc, h2); accum8(acc, h3);
    }
    for (; j < end; j++) {
        int e0 = __ldg(g_vcol + j);
        uint4 h0 = __ldg(Y4 + (size_t)e0 * 32 + lane);
        accum8(acc, h0);
    }
    float s = 1.0f / fmaxf((float)(end - beg), 1.0f);
    float4 o0, o1;
    o0.x = fmaxf(acc[0] * s, 0.0f); o0.y = fmaxf(acc[1] * s, 0.0f);
    o0.z = fmaxf(acc[2] * s, 0.0f); o0.w = fmaxf(acc[3] * s, 0.0f);
    o1.x = fmaxf(acc[4] * s, 0.0f); o1.y = fmaxf(acc[5] * s, 0.0f);
    o1.z = fmaxf(acc[6] * s, 0.0f); o1.w = fmaxf(acc[7] * s, 0.0f);
    __stcs(out + (size_t)v * 64 + lane * 2, o0);
    __stcs(out + (size_t)v * 64 + lane * 2 + 1, o1);
}

extern "C" void kernel_launch(void* const* d_in, const int* in_sizes, int n_in,
                              void* d_out, int out_size) {
    const float* X    = (const float*)d_in[0];
    const float* W    = (const float*)d_in[1];
    const float* bias = (const float*)d_in[2];
    const int* vidx   = (const int*)d_in[3];
    const int* eidx   = (const int*)d_in[4];
    const int nnz     = in_sizes[3];

    void* pCur;
    cudaGetSymbolAddress(&pCur, g_cur);
    cudaMemsetAsync(pCur, 0, sizeof(int) * (NE + NV));

    const int nnz4 = nnz / 4;                  // 200000
    const int histBlocks = (nnz4 + 255) / 256; // 782
    const int convBlocks = (NV * D / 8) / 256; // 12500
    prep<<<histBlocks + convBlocks, 256>>>((const int4*)vidx, (const int4*)eidx,
                                           nnz4, (const float4*)X, histBlocks);
    scan_both<<<2, 1024>>>();
    fill<<<histBlocks, 256>>>((const int4*)vidx, (const int4*)eidx, nnz4);

    gather_v2e<<<(NE + 7) / 8, 256>>>();

    dim3 ggrid(NE_PAD / 128, D / 128);
    gemm_bias<<<ggrid, 256>>>(W, bias);

    gather_e2v<<<(NV + 7) / 8, 256>>>((float4*)d_out);
}